// round 9
// baseline (speedup 1.0000x reference)
#include <cuda_runtime.h>
#include <math.h>
#include <float.h>
#include <stdint.h>

#define NTOK  16384
#define BSZ   4
#define SEQ   4096
#define DIM   2048
#define NEXP  64
#define TOPK  8
#define BM    64     // tokens per block
#define KC    32     // K chunk width
#define NTHREADS 128
#define XS    68     // xsT row stride (floats): 272B, 16B-aligned
#define WS    66     // wsT2 row stride (float2): 528B, 16B-aligned

#define FTZ_MIN 1.17549435e-38f   // FLT_MIN: fp32 normal threshold (FTZ cutoff)

__device__ float g_cnt[BSZ * NEXP];
__device__ float g_ssum[BSZ * NEXP];

__global__ void gate_zero() {
    int i = threadIdx.x;
    if (i < BSZ * NEXP) { g_cnt[i] = 0.f; g_ssum[i] = 0.f; }
}

// Packed fp32x2 FMA: two independent IEEE fp32 RN fused FMAs per instruction.
// Each half is bit-identical to scalar fmaf — per-output chains unchanged.
__device__ __forceinline__ void ffma2(unsigned long long& d,
                                      unsigned long long a, unsigned long long b) {
    asm("fma.rn.f32x2 %0, %1, %2, %3;" : "=l"(d) : "l"(a), "l"(b), "l"(d));
}

__global__ __launch_bounds__(NTHREADS) void gate_main(
    const float* __restrict__ x, const float* __restrict__ w,
    const float* __restrict__ bias, float* __restrict__ out)
{
    __shared__ float  xsT[KC * XS];       // [k][token]        8704 B
    __shared__ float2 wsT2[KC * WS];      // [k][expert]=(w,w) 16896 B
    __shared__ float  lg[BM][NEXP + 1];   //                   16640 B
    __shared__ float  s_max[BM];
    __shared__ float  s_inv[BM];
    __shared__ float  s_cnt[NEXP];

    const int tid = threadIdx.x;
    const int et  = tid & 15;   // experts et*4 .. et*4+3
    const int tt  = tid >> 4;   // tokens  tt*8 .. tt*8+7
    const int base = blockIdx.x * BM;

    // 16 packed accumulators: token-pair (2i,2i+1) x expert j. 0ULL == (0.f,0.f)
    unsigned long long acc[4][4];
    #pragma unroll
    for (int i = 0; i < 4; i++)
        #pragma unroll
        for (int j = 0; j < 4; j++) acc[i][j] = 0ULL;

    const float* xb = x + (size_t)base * DIM;

    for (int kc = 0; kc < DIM; kc += KC) {
        // cooperative load: transpose x into [k][token]; w into [k][expert] duplicated
        #pragma unroll
        for (int it = 0; it < 4; it++) {
            int idx = tid + it * NTHREADS;       // 0..511 float4 slots
            int r = idx >> 3;                    // row (token / expert)
            int c = (idx & 7) << 2;              // k offset
            float4 v = *(const float4*)(xb + (size_t)r * DIM + kc + c);
            xsT[(c    ) * XS + r] = v.x;
            xsT[(c + 1) * XS + r] = v.y;
            xsT[(c + 2) * XS + r] = v.z;
            xsT[(c + 3) * XS + r] = v.w;
            float4 u = *(const float4*)(w + (size_t)r * DIM + kc + c);
            wsT2[(c    ) * WS + r] = make_float2(u.x, u.x);
            wsT2[(c + 1) * WS + r] = make_float2(u.y, u.y);
            wsT2[(c + 2) * WS + r] = make_float2(u.z, u.z);
            wsT2[(c + 3) * WS + r] = make_float2(u.w, u.w);
        }
        __syncthreads();

        // K strictly ascending; each output = one packed lane of an unbroken chain
        #pragma unroll 8
        for (int k = 0; k < KC; k++) {
            const ulonglong2 xa = *(const ulonglong2*)&xsT[k * XS + tt * 8];      // tok 0-3
            const ulonglong2 xc = *(const ulonglong2*)&xsT[k * XS + tt * 8 + 4];  // tok 4-7
            const ulonglong2 w01 = *(const ulonglong2*)&wsT2[k * WS + et * 4];     // (w0,w0),(w1,w1)
            const ulonglong2 w23 = *(const ulonglong2*)&wsT2[k * WS + et * 4 + 2]; // (w2,w2),(w3,w3)
            ffma2(acc[0][0], xa.x, w01.x); ffma2(acc[0][1], xa.x, w01.y);
            ffma2(acc[0][2], xa.x, w23.x); ffma2(acc[0][3], xa.x, w23.y);
            ffma2(acc[1][0], xa.y, w01.x); ffma2(acc[1][1], xa.y, w01.y);
            ffma2(acc[1][2], xa.y, w23.x); ffma2(acc[1][3], xa.y, w23.y);
            ffma2(acc[2][0], xc.x, w01.x); ffma2(acc[2][1], xc.x, w01.y);
            ffma2(acc[2][2], xc.x, w23.x); ffma2(acc[2][3], xc.x, w23.y);
            ffma2(acc[3][0], xc.y, w01.x); ffma2(acc[3][1], xc.y, w01.y);
            ffma2(acc[3][2], xc.y, w23.x); ffma2(acc[3][3], xc.y, w23.y);
        }
        __syncthreads();
    }

    // unpack + bias -> logits smem
    #pragma unroll
    for (int i = 0; i < 4; i++) {
        int row = tt * 8 + i * 2;
        #pragma unroll
        for (int j = 0; j < 4; j++) {
            int col = et * 4 + j;
            float b  = bias[col];
            float lo = __uint_as_float((unsigned)(acc[i][j] & 0xFFFFFFFFull));
            float hi = __uint_as_float((unsigned)(acc[i][j] >> 32));
            lg[row    ][col] = lo + b;
            lg[row + 1][col] = hi + b;
        }
    }
    if (tid < NEXP) s_cnt[tid] = 0.f;
    __syncthreads();

    // per-token softmax (FTZ) + top-8 on SCORES, ties -> lower index (lax.top_k)
    if (tid < BM) {
        const int t = tid;
        float m = -FLT_MAX;
        for (int e = 0; e < NEXP; e++) m = fmaxf(m, lg[t][e]);

        float sum = 0.f;
        for (int e = 0; e < NEXP; e++) {
            float s = expf(lg[t][e] - m);
            if (s < FTZ_MIN) s = 0.f;
            sum += s;
        }
        float inv_sum = 1.f / sum;

        float bv[TOPK]; int bi[TOPK];
        #pragma unroll
        for (int r = 0; r < TOPK; r++) { bv[r] = -FLT_MAX; bi[r] = 0; }

        for (int e = 0; e < NEXP; e++) {
            float s = expf(lg[t][e] - m);
            if (s < FTZ_MIN) s = 0.f;
            float q = s * inv_sum;
            if (q < FTZ_MIN) q = 0.f;
            if (q > bv[TOPK - 1]) {
                int p = TOPK - 1;
                while (p > 0 && q > bv[p - 1]) {
                    bv[p] = bv[p - 1]; bi[p] = bi[p - 1]; p--;
                }
                bv[p] = q; bi[p] = e;
            }
        }
        s_max[t] = m;
        s_inv[t] = inv_sum;

        float den = 1e-20f;
        #pragma unroll
        for (int r = 0; r < TOPK; r++) den += bv[r];
        float inv = 1.f / den;

        const int token = base + t;
        #pragma unroll
        for (int r = 0; r < TOPK; r++)
            out[(size_t)token * TOPK + r] = (float)bi[r];
        #pragma unroll
        for (int r = 0; r < TOPK; r++)
            out[(size_t)NTOK * TOPK + (size_t)token * TOPK + r] = bv[r] * inv;
        #pragma unroll
        for (int r = 0; r < TOPK; r++)
            atomicAdd(&s_cnt[bi[r]], 1.f);
    }
    __syncthreads();

    // per-expert column sums of (flushed) softmax scores over this block's tokens
    if (tid < NEXP) {
        const int e = tid;
        float cs = 0.f;
        for (int t = 0; t < BM; t++) {
            float s = expf(lg[t][e] - s_max[t]);
            if (s < FTZ_MIN) s = 0.f;
            float q = s * s_inv[t];
            if (q < FTZ_MIN) q = 0.f;
            cs += q;
        }
        const int b = base / SEQ;
        atomicAdd(&g_ssum[b * NEXP + e], cs);
        atomicAdd(&g_cnt[b * NEXP + e], s_cnt[e]);
    }
}

__global__ void gate_finalize(float* __restrict__ out) {
    __shared__ float red[256];
    const int i = threadIdx.x;
    // aux = mean_b sum_e (cnt/(SEQ*K/E)) * (ssum/SEQ)
    float v = (g_cnt[i] * (1.f / 512.f)) * (g_ssum[i] * (1.f / 4096.f));
    red[i] = v;
    __syncthreads();
    for (int s = 128; s > 0; s >>= 1) {
        if (i < s) red[i] += red[i + s];
        __syncthreads();
    }
    if (i == 0) out[2 * NTOK * TOPK] = red[0] * (1.f / BSZ);
}

extern "C" void kernel_launch(void* const* d_in, const int* in_sizes, int n_in,
                              void* d_out, int out_size) {
    const float* x    = (const float*)d_in[0];   // [4,4096,2048] f32
    const float* wgt  = (const float*)d_in[1];   // [64,2048]     f32
    const float* bias = (const float*)d_in[2];   // [64]          f32
    float* out = (float*)d_out;                  // [idx 131072][w 131072][aux 1]

    gate_zero<<<1, 256>>>();
    gate_main<<<NTOK / BM, NTHREADS>>>(x, wgt, bias, out);
    gate_finalize<<<1, 256>>>(out);
}

// round 10
// speedup vs baseline: 1.6688x; 1.6688x over previous
#include <cuda_runtime.h>
#include <math.h>
#include <float.h>
#include <stdint.h>

#define NTOK  16384
#define BSZ   4
#define SEQ   4096
#define DIM   2048
#define NEXP  64
#define TOPK  8
#define BM    64     // tokens per block
#define KC    64     // K chunk width (floats)
#define NTHREADS 128
#define XSS   68     // xs row stride in floats (272B, 16B-aligned)
#define WK4   69     // wq4 k4-stride in float4 (odd mod 8 -> conflict-free stores)
#define WJ4   17     // wq4 j-stride in float4

#define FTZ_MIN 1.17549435e-38f   // FLT_MIN: fp32 normal threshold (FTZ cutoff)

__device__ float g_cnt[BSZ * NEXP];
__device__ float g_ssum[BSZ * NEXP];

__global__ void gate_zero() {
    int i = threadIdx.x;
    if (i < BSZ * NEXP) { g_cnt[i] = 0.f; g_ssum[i] = 0.f; }
}

__global__ __launch_bounds__(NTHREADS) void gate_main(
    const float* __restrict__ x, const float* __restrict__ w,
    const float* __restrict__ bias, float* __restrict__ out)
{
    __shared__ float  xs[BM * XSS];            // [token][k]  17408 B
    __shared__ float4 wq4[(KC / 4) * WK4];     // [k4][j][et] 17664 B
    __shared__ float  lg[BM][NEXP + 1];        //             16640 B
    __shared__ float  s_max[BM];
    __shared__ float  s_inv[BM];
    __shared__ float  s_cnt[NEXP];

    const int tid = threadIdx.x;
    const int et  = tid & 15;   // experts et*4 .. et*4+3
    const int tt  = tid >> 4;   // tokens  tt*8 .. tt*8+7
    const int base = blockIdx.x * BM;

    float acc[8][4];            // (token i, expert j) — same chains as round 8
    #pragma unroll
    for (int i = 0; i < 8; i++)
        #pragma unroll
        for (int j = 0; j < 4; j++) acc[i][j] = 0.f;

    const float* xb = x + (size_t)base * DIM;

    for (int kc = 0; kc < DIM; kc += KC) {
        // cooperative load: x -> xs[row][k] (float4); w -> wq4[k4][j][et4] layout
        #pragma unroll
        for (int it = 0; it < 8; it++) {
            int idx = tid + it * NTHREADS;     // 0..1023 float4 slots
            int r = idx >> 4;                  // row 0..63
            int c = (idx & 15) << 2;           // k offset 0..60
            float4 v = *(const float4*)(xb + (size_t)r * DIM + kc + c);
            *(float4*)&xs[r * XSS + c] = v;
            float4 u = *(const float4*)(w + (size_t)r * DIM + kc + c);
            wq4[(c >> 2) * WK4 + (r & 3) * WJ4 + (r >> 2)] = u;
        }
        __syncthreads();

        // K strictly ascending per accumulator (x->y->z->w): bitwise round-8 chains
        #pragma unroll 2
        for (int k4 = 0; k4 < KC / 4; k4++) {
            float4 wv[4];
            #pragma unroll
            for (int j = 0; j < 4; j++)
                wv[j] = wq4[k4 * WK4 + j * WJ4 + et];
            float4 xv[8];
            #pragma unroll
            for (int i = 0; i < 8; i++)
                xv[i] = *(const float4*)&xs[(tt * 8 + i) * XSS + k4 * 4];

            #pragma unroll
            for (int i = 0; i < 8; i++)
                #pragma unroll
                for (int j = 0; j < 4; j++)
                    acc[i][j] = fmaf(xv[i].x, wv[j].x, acc[i][j]);
            #pragma unroll
            for (int i = 0; i < 8; i++)
                #pragma unroll
                for (int j = 0; j < 4; j++)
                    acc[i][j] = fmaf(xv[i].y, wv[j].y, acc[i][j]);
            #pragma unroll
            for (int i = 0; i < 8; i++)
                #pragma unroll
                for (int j = 0; j < 4; j++)
                    acc[i][j] = fmaf(xv[i].z, wv[j].z, acc[i][j]);
            #pragma unroll
            for (int i = 0; i < 8; i++)
                #pragma unroll
                for (int j = 0; j < 4; j++)
                    acc[i][j] = fmaf(xv[i].w, wv[j].w, acc[i][j]);
        }
        __syncthreads();
    }

    // logits + bias -> smem
    #pragma unroll
    for (int j = 0; j < 4; j++) {
        float b = bias[et * 4 + j];
        #pragma unroll
        for (int i = 0; i < 8; i++)
            lg[tt * 8 + i][et * 4 + j] = acc[i][j] + b;
    }
    if (tid < NEXP) s_cnt[tid] = 0.f;
    __syncthreads();

    // per-token softmax (FTZ) + top-8 on SCORES, ties -> lower index (lax.top_k)
    if (tid < BM) {
        const int t = tid;
        float m = -FLT_MAX;
        for (int e = 0; e < NEXP; e++) m = fmaxf(m, lg[t][e]);

        float sum = 0.f;
        for (int e = 0; e < NEXP; e++) {
            float s = expf(lg[t][e] - m);
            if (s < FTZ_MIN) s = 0.f;
            sum += s;
        }
        float inv_sum = 1.f / sum;

        float bv[TOPK]; int bi[TOPK];
        #pragma unroll
        for (int r = 0; r < TOPK; r++) { bv[r] = -FLT_MAX; bi[r] = 0; }

        for (int e = 0; e < NEXP; e++) {
            float s = expf(lg[t][e] - m);
            if (s < FTZ_MIN) s = 0.f;
            float q = s * inv_sum;
            if (q < FTZ_MIN) q = 0.f;
            if (q > bv[TOPK - 1]) {
                int p = TOPK - 1;
                while (p > 0 && q > bv[p - 1]) {
                    bv[p] = bv[p - 1]; bi[p] = bi[p - 1]; p--;
                }
                bv[p] = q; bi[p] = e;
            }
        }
        s_max[t] = m;
        s_inv[t] = inv_sum;

        float den = 1e-20f;
        #pragma unroll
        for (int r = 0; r < TOPK; r++) den += bv[r];
        float inv = 1.f / den;

        const int token = base + t;
        #pragma unroll
        for (int r = 0; r < TOPK; r++)
            out[(size_t)token * TOPK + r] = (float)bi[r];
        #pragma unroll
        for (int r = 0; r < TOPK; r++)
            out[(size_t)NTOK * TOPK + (size_t)token * TOPK + r] = bv[r] * inv;
        #pragma unroll
        for (int r = 0; r < TOPK; r++)
            atomicAdd(&s_cnt[bi[r]], 1.f);
    }
    __syncthreads();

    // per-expert column sums of (flushed) softmax scores over this block's tokens
    if (tid < NEXP) {
        const int e = tid;
        float cs = 0.f;
        for (int t = 0; t < BM; t++) {
            float s = expf(lg[t][e] - s_max[t]);
            if (s < FTZ_MIN) s = 0.f;
            float q = s * s_inv[t];
            if (q < FTZ_MIN) q = 0.f;
            cs += q;
        }
        const int b = base / SEQ;
        atomicAdd(&g_ssum[b * NEXP + e], cs);
        atomicAdd(&g_cnt[b * NEXP + e], s_cnt[e]);
    }
}

__global__ void gate_finalize(float* __restrict__ out) {
    __shared__ float red[256];
    const int i = threadIdx.x;
    // aux = mean_b sum_e (cnt/(SEQ*K/E)) * (ssum/SEQ)
    float v = (g_cnt[i] * (1.f / 512.f)) * (g_ssum[i] * (1.f / 4096.f));
    red[i] = v;
    __syncthreads();
    for (int s = 128; s > 0; s >>= 1) {
        if (i < s) red[i] += red[i + s];
        __syncthreads();
    }
    if (i == 0) out[2 * NTOK * TOPK] = red[0] * (1.f / BSZ);
}

extern "C" void kernel_launch(void* const* d_in, const int* in_sizes, int n_in,
                              void* d_out, int out_size) {
    const float* x    = (const float*)d_in[0];   // [4,4096,2048] f32
    const float* wgt  = (const float*)d_in[1];   // [64,2048]     f32
    const float* bias = (const float*)d_in[2];   // [64]          f32
    float* out = (float*)d_out;                  // [idx 131072][w 131072][aux 1]

    gate_zero<<<1, 256>>>();
    gate_main<<<NTOK / BM, NTHREADS>>>(x, wgt, bias, out);
    gate_finalize<<<1, 256>>>(out);
}